// round 10
// baseline (speedup 1.0000x reference)
#include <cuda_runtime.h>
#include <math.h>

#define NPOS 512
#define NALL 1024
#define DIM  512
#define EPSV 1e-5f
#define COSEPS 1e-8f
#define TILE 64
#define DK   64           // k-chunk, double-buffered
#define SPAD 68           // padded smem row (floats)
#define NTHR 512
#define NCHUNK (DIM / DK) // 8

#define SMEM_FLOATS (4 * DK * SPAD + 2 * DK)
#define SMEM_BYTES  (SMEM_FLOATS * 4)

// ---------------- device scratch ----------------
__device__ float g_rnorm[NALL];
__device__ float g_t1[NPOS];     // t1 + s3 (pos rows)
__device__ float g_t2[NALL];     // t2 + s3 (all rows)
__device__ float g_deno[NPOS];
__device__ float g_total;
__device__ unsigned g_negdone;
__device__ unsigned g_alldone;

__device__ __forceinline__ float warp_sum(float v) {
#pragma unroll
    for (int o = 16; o; o >>= 1) v += __shfl_xor_sync(0xffffffffu, v, o);
    return v;
}

__device__ __forceinline__ float sp(float x) {   // softplus, stable
    return fmaxf(x, 0.f) + log1pf(expf(-fabsf(x)));
}

// m16n8k8 tf32 mma, D += A*B (fp32 accum). Raw fp32 bits as tf32 (truncation).
__device__ __forceinline__ void mma_tf32(float d[4],
                                         unsigned a0, unsigned a1, unsigned a2, unsigned a3,
                                         unsigned b0, unsigned b1) {
    asm volatile(
        "mma.sync.aligned.m16n8k8.row.col.f32.tf32.tf32.f32 "
        "{%0,%1,%2,%3}, {%4,%5,%6,%7}, {%8,%9}, {%0,%1,%2,%3};"
        : "+f"(d[0]), "+f"(d[1]), "+f"(d[2]), "+f"(d[3])
        : "r"(a0), "r"(a1), "r"(a2), "r"(a3), "r"(b0), "r"(b1));
}

// ---------------- kernel 1: per-row norm, t1+s3, t2+s3 (+ scratch init) --------
__global__ void row_kernel(const float* __restrict__ pos,
                           const float* __restrict__ neg,
                           const float* __restrict__ w) {
    int row = blockIdx.x;                       // 0..1023
    int t = threadIdx.x;                        // 128
    if (t == 0) {
        if (row < NPOS) g_deno[row] = 0.f;
        if (row == 0) { g_total = 0.f; g_negdone = 0u; g_alldone = 0u; }
    }
    const float* src = (row < NPOS) ? (pos + row * DIM) : (neg + (row - NPOS) * DIM);
    float4 v  = ((const float4*)src)[t];
    float4 u1 = ((const float4*)w)[t];
    float4 u2 = ((const float4*)(w + DIM))[t];
    float4 u3 = ((const float4*)(w + 2 * DIM))[t];
    float ss = v.x * v.x; ss = fmaf(v.y, v.y, ss); ss = fmaf(v.z, v.z, ss); ss = fmaf(v.w, v.w, ss);
    float d1 = v.x * u1.x; d1 = fmaf(v.y, u1.y, d1); d1 = fmaf(v.z, u1.z, d1); d1 = fmaf(v.w, u1.w, d1);
    float d2 = v.x * u2.x; d2 = fmaf(v.y, u2.y, d2); d2 = fmaf(v.z, u2.z, d2); d2 = fmaf(v.w, u2.w, d2);
    float d3 = v.x * u3.x; d3 = fmaf(v.y, u3.y, d3); d3 = fmaf(v.z, u3.z, d3); d3 = fmaf(v.w, u3.w, d3);
    ss = warp_sum(ss); d1 = warp_sum(d1); d2 = warp_sum(d2); d3 = warp_sum(d3);
    __shared__ float red[4][4];
    int wid = t >> 5, lid = t & 31;
    if (lid == 0) { red[0][wid] = ss; red[1][wid] = d1; red[2][wid] = d2; red[3][wid] = d3; }
    __syncthreads();
    if (t == 0) {
        float S  = red[0][0] + red[0][1] + red[0][2] + red[0][3];
        float D1 = red[1][0] + red[1][1] + red[1][2] + red[1][3];
        float D2 = red[2][0] + red[2][1] + red[2][2] + red[2][3];
        float D3 = red[3][0] + red[3][1] + red[3][2] + red[3][3];
        g_rnorm[row] = 1.f / fmaxf(sqrtf(S), COSEPS);
        g_t2[row] = D2 + D3;                    // t2 + s3
        if (row < NPOS) g_t1[row] = D1 + D3;    // t1 + s3
    }
}

// ---------------- kernel 2: fused pair kernel (tf32 mma dot + scalar min) -----
// grid (16, 8): bx<8 -> pos-vs-pos (loss1 + bce), bx>=8 -> pos-vs-neg (deno + bce)
// 16 warps in a 4x4 grid over the 64x64 tile; each warp owns a 16x16 patch:
//   dot via 2x m16n8k8 tf32 mma, min-term scalar at mma D-fragment coords.
__global__ void __launch_bounds__(NTHR, 1) pair_kernel(
    const float* __restrict__ pos, const float* __restrict__ neg,
    const float* __restrict__ w, const float* __restrict__ bptr,
    float* __restrict__ out)
{
    extern __shared__ float smem[];
    float (*sA)[DK][SPAD] = (float (*)[DK][SPAD])(smem);
    float (*sB)[DK][SPAD] = (float (*)[DK][SPAD])(smem + 2 * DK * SPAD);
    float (*sW)[DK]       = (float (*)[DK])(smem + 4 * DK * SPAD);
    __shared__ float sRed[16];

    const int t    = threadIdx.x;
    const int lane = t & 31;
    const int wrp  = t >> 5;         // 0..15
    const int wr   = wrp >> 2;       // n-block (16 rows)
    const int wc   = wrp & 3;        // m-block (16 cols)
    const int la   = lane & 3;       // thread-in-group
    const int lg   = lane >> 2;      // group id (0..7)
    const int nb   = wr * 16;        // tile-local n base
    const int mb   = wc * 16;        // tile-local m base

    const int n0 = blockIdx.y * TILE;
    const int m0 = blockIdx.x * TILE;
    const bool pos_half = (m0 < NPOS);
    const float* Bsrc = pos_half ? pos : neg;
    const int mrow0 = pos_half ? m0 : (m0 - NPOS);
    const float* w3 = w + 2 * DIM;

    // dot accumulators: D[2 tiles][4]; min accumulators mnv[i 2 rows][j 4 cols]
    float D0[4] = {0.f, 0.f, 0.f, 0.f};
    float D1[4] = {0.f, 0.f, 0.f, 0.f};
    float mnv[2][4];
#pragma unroll
    for (int i = 0; i < 2; i++)
#pragma unroll
        for (int j = 0; j < 4; j++) mnv[i][j] = 0.f;

    // loader mapping: lc = d within chunk (0..63), lr = row group (0..7)
    const int lc = t & 63;
    const int lr = t >> 6;

    float pfA[8], pfB[8], pfW;
#define LOADC(Dz) do {                                               \
    _Pragma("unroll")                                                \
    for (int q = 0; q < 8; q++) {                                    \
        int r = lr + 8 * q;                                          \
        pfA[q] = pos [(n0 + r)    * DIM + (Dz) + lc];                \
        pfB[q] = Bsrc[(mrow0 + r) * DIM + (Dz) + lc];                \
    }                                                                \
    if (t < DK) pfW = w3[(Dz) + t];                                  \
} while (0)

#define STORC(buf) do {                                              \
    _Pragma("unroll")                                                \
    for (int q = 0; q < 8; q++) {                                    \
        int r = lr + 8 * q;                                          \
        sA[buf][lc][r] = pfA[q];                                     \
        sB[buf][lc][r] = pfB[q];                                     \
    }                                                                \
    if (t < DK) sW[buf][t] = pfW;                                    \
} while (0)

    LOADC(0);
    STORC(0);
    __syncthreads();

    for (int c = 0; c < NCHUNK; c++) {
        const int cur = c & 1;
        if (c < NCHUNK - 1) LOADC((c + 1) * DK);   // LDGs land during compute

        // ---- min-term scalar loop (alu FMNMX + fma FFMA) ----
#pragma unroll 16
        for (int kk = 0; kk < DK; kk++) {
            float a0 = sA[cur][kk][nb + lg];
            float a1 = sA[cur][kk][nb + lg + 8];
            float2 bl = *(const float2*)&sB[cur][kk][mb + 2 * la];
            float2 bh = *(const float2*)&sB[cur][kk][mb + 2 * la + 8];
            float a[2] = {a0, a1};
            float b[4] = {bl.x, bl.y, bh.x, bh.y};
            float wv = sW[cur][kk];
#pragma unroll
            for (int i = 0; i < 2; i++)
#pragma unroll
                for (int j = 0; j < 4; j++)
                    mnv[i][j] = fmaf(fminf(a[i], b[j]), wv, mnv[i][j]);
        }

        // ---- dot via tf32 mma: 8 k8-steps over this chunk ----
#pragma unroll
        for (int ks = 0; ks < 8; ks++) {
            const int k0 = ks * 8;
            unsigned fa0 = __float_as_uint(sA[cur][k0 + la    ][nb + lg]);
            unsigned fa1 = __float_as_uint(sA[cur][k0 + la    ][nb + lg + 8]);
            unsigned fa2 = __float_as_uint(sA[cur][k0 + la + 4][nb + lg]);
            unsigned fa3 = __float_as_uint(sA[cur][k0 + la + 4][nb + lg + 8]);
            unsigned fb0 = __float_as_uint(sB[cur][k0 + la    ][mb + lg]);
            unsigned fb1 = __float_as_uint(sB[cur][k0 + la + 4][mb + lg]);
            unsigned fc0 = __float_as_uint(sB[cur][k0 + la    ][mb + lg + 8]);
            unsigned fc1 = __float_as_uint(sB[cur][k0 + la + 4][mb + lg + 8]);
            mma_tf32(D0, fa0, fa1, fa2, fa3, fb0, fb1);   // cols mb..mb+7
            mma_tf32(D1, fa0, fa1, fa2, fa3, fc0, fc1);   // cols mb+8..mb+15
        }

        if (c < NCHUNK - 1) STORC(1 - cur);
        __syncthreads();
    }

    // reorganize dot to [i 2 rows][j 4 cols] matching mnv
    float dotv[2][4];
    dotv[0][0] = D0[0]; dotv[0][1] = D0[1]; dotv[1][0] = D0[2]; dotv[1][1] = D0[3];
    dotv[0][2] = D1[0]; dotv[0][3] = D1[1]; dotv[1][2] = D1[2]; dotv[1][3] = D1[3];

    // ---- epilogue ----
    int gn[2];
    float rn_n[2], t1v[2], rn_m[4], t2v[4];
#pragma unroll
    for (int i = 0; i < 2; i++) {
        gn[i] = n0 + nb + lg + 8 * i;
        rn_n[i] = g_rnorm[gn[i]];
        t1v[i]  = g_t1[gn[i]];     // includes s3[n]
    }
#pragma unroll
    for (int j = 0; j < 4; j++) {
        int gm = m0 + mb + 2 * la + (j & 1) + 8 * (j >> 1);
        rn_m[j] = g_rnorm[gm];
        t2v[j]  = g_t2[gm];        // includes s3[m]
    }
    float bias = __ldg(bptr);

    float part = 0.f;

    if (!pos_half) {
        // ---- negative half: bce(label 0) + deno ----
        float bce = 0.f, dl[2] = {0.f, 0.f};
#pragma unroll
        for (int i = 0; i < 2; i++) {
#pragma unroll
            for (int j = 0; j < 4; j++) {
                float cc = dotv[i][j] * rn_n[i] * rn_m[j];
                float logit = t1v[i] + t2v[j] - 2.f * mnv[i][j] + bias;
                bce += sp(logit);
                dl[i] += expf(cc);
            }
        }
        // reduce over the 4 lanes (la) sharing each row; lanes differ in bits 0-1
#pragma unroll
        for (int i = 0; i < 2; i++) {
            float v = dl[i];
            v += __shfl_xor_sync(0xffffffffu, v, 1);
            v += __shfl_xor_sync(0xffffffffu, v, 2);
            if (la == 0) atomicAdd(&g_deno[gn[i]], v);
        }
        __threadfence();                       // publish deno before negdone arrive
        part = bce * (1.0f / (float)NALL);
    } else {
        // ---- positive half: wait for deno, then bce(label 1) + contrastive ----
        if (t == 0) {
            while (atomicCAS(&g_negdone, 64u, 64u) != 64u) { __nanosleep(200); }
        }
        __syncthreads();
        __threadfence();
        float dn[2];
#pragma unroll
        for (int i = 0; i < 2; i++) dn[i] = __ldcg(&g_deno[gn[i]]);

        float bce = 0.f, l1 = 0.f;
#pragma unroll
        for (int i = 0; i < 2; i++) {
#pragma unroll
            for (int j = 0; j < 4; j++) {
                float cc = dotv[i][j] * rn_n[i] * rn_m[j];
                float logit = t1v[i] + t2v[j] - 2.f * mnv[i][j] + bias;
                bce += sp(-logit);
                l1 += logf(dn[i] + expf(cc) + EPSV) - cc;  // -log(e^c/(deno+e^c+eps))
            }
        }
        part = bce * (1.0f / (float)NALL) + l1;
    }

    // ---- block reduce + global accumulate + completion protocol ----
    float v = warp_sum(part);
    if ((t & 31) == 0) sRed[t >> 5] = v;
    __syncthreads();
    if (t == 0) {
        float s = 0.f;
#pragma unroll
        for (int k = 0; k < 16; k++) s += sRed[k];
        atomicAdd(&g_total, s);
        __threadfence();
        if (!pos_half) atomicAdd(&g_negdone, 1u);
        unsigned old = atomicAdd(&g_alldone, 1u);
        if (old == 127u) {
            __threadfence();
            out[0] = atomicAdd(&g_total, 0.f);
        }
    }
}

// ---------------- launch ----------------
extern "C" void kernel_launch(void* const* d_in, const int* in_sizes, int n_in,
                              void* d_out, int out_size) {
    const float* pos = (const float*)d_in[0];   // [512,512]
    const float* neg = (const float*)d_in[1];   // [512,512]
    const float* w   = (const float*)d_in[2];   // [1,1536]
    const float* b   = (const float*)d_in[3];   // [1]
    float* out = (float*)d_out;

    cudaFuncSetAttribute(pair_kernel,
                         cudaFuncAttributeMaxDynamicSharedMemorySize, SMEM_BYTES);

    row_kernel<<<NALL, 128>>>(pos, neg, w);
    dim3 grid(NALL / TILE, NPOS / TILE);        // (16, 8) — one wave, 128 blocks
    pair_kernel<<<grid, NTHR, SMEM_BYTES>>>(pos, neg, w, b, out);
}

// round 11
// speedup vs baseline: 1.0917x; 1.0917x over previous
#include <cuda_runtime.h>
#include <math.h>

#define NPOS 512
#define NALL 1024
#define DIM  512
#define EPSV 1e-5f
#define COSEPS 1e-8f
#define TILE 64
#define DK   64           // k-chunk, double-buffered
#define SPAD 68           // padded smem row (floats)
#define NTHR 512
#define NCHUNK (DIM / DK) // 8

#define SMEM_FLOATS (4 * DK * SPAD + 2 * DK)
#define SMEM_BYTES  (SMEM_FLOATS * 4)

// ---------------- device scratch ----------------
__device__ float g_rnorm[NALL];
__device__ float g_t1[NPOS];     // t1 + s3 (pos rows)
__device__ float g_t2[NALL];     // t2 + s3 (all rows)
__device__ float g_deno[NPOS];
__device__ float g_total;
__device__ unsigned g_negdone;
__device__ unsigned g_alldone;

__device__ __forceinline__ float warp_sum(float v) {
#pragma unroll
    for (int o = 16; o; o >>= 1) v += __shfl_xor_sync(0xffffffffu, v, o);
    return v;
}

__device__ __forceinline__ float sp(float x) {   // softplus, stable
    return fmaxf(x, 0.f) + log1pf(expf(-fabsf(x)));
}

// m16n8k8 tf32 mma, D += A*B (fp32 accum). Raw fp32 bits as tf32 (truncation).
__device__ __forceinline__ void mma_tf32(float d[4],
                                         unsigned a0, unsigned a1, unsigned a2, unsigned a3,
                                         unsigned b0, unsigned b1) {
    asm volatile(
        "mma.sync.aligned.m16n8k8.row.col.f32.tf32.tf32.f32 "
        "{%0,%1,%2,%3}, {%4,%5,%6,%7}, {%8,%9}, {%0,%1,%2,%3};"
        : "+f"(d[0]), "+f"(d[1]), "+f"(d[2]), "+f"(d[3])
        : "r"(a0), "r"(a1), "r"(a2), "r"(a3), "r"(b0), "r"(b1));
}

// ---------------- kernel 1: per-row norm, t1+s3, t2+s3 (+ scratch init) --------
__global__ void row_kernel(const float* __restrict__ pos,
                           const float* __restrict__ neg,
                           const float* __restrict__ w) {
    int row = blockIdx.x;                       // 0..1023
    int t = threadIdx.x;                        // 128
    if (t == 0) {
        if (row < NPOS) g_deno[row] = 0.f;
        if (row == 0) { g_total = 0.f; g_negdone = 0u; g_alldone = 0u; }
    }
    const float* src = (row < NPOS) ? (pos + row * DIM) : (neg + (row - NPOS) * DIM);
    float4 v  = ((const float4*)src)[t];
    float4 u1 = ((const float4*)w)[t];
    float4 u2 = ((const float4*)(w + DIM))[t];
    float4 u3 = ((const float4*)(w + 2 * DIM))[t];
    float ss = v.x * v.x; ss = fmaf(v.y, v.y, ss); ss = fmaf(v.z, v.z, ss); ss = fmaf(v.w, v.w, ss);
    float d1 = v.x * u1.x; d1 = fmaf(v.y, u1.y, d1); d1 = fmaf(v.z, u1.z, d1); d1 = fmaf(v.w, u1.w, d1);
    float d2 = v.x * u2.x; d2 = fmaf(v.y, u2.y, d2); d2 = fmaf(v.z, u2.z, d2); d2 = fmaf(v.w, u2.w, d2);
    float d3 = v.x * u3.x; d3 = fmaf(v.y, u3.y, d3); d3 = fmaf(v.z, u3.z, d3); d3 = fmaf(v.w, u3.w, d3);
    ss = warp_sum(ss); d1 = warp_sum(d1); d2 = warp_sum(d2); d3 = warp_sum(d3);
    __shared__ float red[4][4];
    int wid = t >> 5, lid = t & 31;
    if (lid == 0) { red[0][wid] = ss; red[1][wid] = d1; red[2][wid] = d2; red[3][wid] = d3; }
    __syncthreads();
    if (t == 0) {
        float S  = red[0][0] + red[0][1] + red[0][2] + red[0][3];
        float D1 = red[1][0] + red[1][1] + red[1][2] + red[1][3];
        float D2 = red[2][0] + red[2][1] + red[2][2] + red[2][3];
        float D3 = red[3][0] + red[3][1] + red[3][2] + red[3][3];
        g_rnorm[row] = 1.f / fmaxf(sqrtf(S), COSEPS);
        g_t2[row] = D2 + D3;                    // t2 + s3
        if (row < NPOS) g_t1[row] = D1 + D3;    // t1 + s3
    }
}

// ---------------- kernel 2: fused pair kernel (tf32 mma dot + scalar min) -----
// grid (16, 8): bx<8 -> pos-vs-pos (loss1 + bce), bx>=8 -> pos-vs-neg (deno + bce)
// mma dot on warp 16x16 patches; min-term at R9-optimal scalar coords;
// coordinate reconciliation via one smem exchange after the mainloop.
__global__ void __launch_bounds__(NTHR, 1) pair_kernel(
    const float* __restrict__ pos, const float* __restrict__ neg,
    const float* __restrict__ w, const float* __restrict__ bptr,
    float* __restrict__ out)
{
    extern __shared__ float smem[];
    float (*sA)[DK][SPAD] = (float (*)[DK][SPAD])(smem);
    float (*sB)[DK][SPAD] = (float (*)[DK][SPAD])(smem + 2 * DK * SPAD);
    float (*sW)[DK]       = (float (*)[DK])(smem + 4 * DK * SPAD);
    float (*sX)[65]       = (float (*)[65])(smem);   // exchange buffer, aliases sA after mainloop
    __shared__ float sRed[16];

    const int t    = threadIdx.x;
    const int lane = t & 31;
    const int wrp  = t >> 5;         // 0..15
    const int nb   = (wrp >> 2) * 16;   // warp n base
    const int mb   = (wrp & 3)  * 16;   // warp m base
    const int la   = lane & 3;
    const int lg   = lane >> 2;

    // min-loop coords (R9): 2 adjacent rows, 4 adjacent cols
    const int tx = t & 15;
    const int ty = t >> 4;           // 0..31

    const int n0 = blockIdx.y * TILE;
    const int m0 = blockIdx.x * TILE;
    const bool pos_half = (m0 < NPOS);
    const float* Bsrc = pos_half ? pos : neg;
    const int mrow0 = pos_half ? m0 : (m0 - NPOS);
    const float* w3 = w + 2 * DIM;

    float D0[4] = {0.f, 0.f, 0.f, 0.f};
    float D1[4] = {0.f, 0.f, 0.f, 0.f};
    float mnv[2][4];
#pragma unroll
    for (int i = 0; i < 2; i++)
#pragma unroll
        for (int j = 0; j < 4; j++) mnv[i][j] = 0.f;

    const int lc = t & 63;
    const int lr = t >> 6;

    float pfA[8], pfB[8], pfW;
#define LOADC(Dz) do {                                               \
    _Pragma("unroll")                                                \
    for (int q = 0; q < 8; q++) {                                    \
        int r = lr + 8 * q;                                          \
        pfA[q] = pos [(n0 + r)    * DIM + (Dz) + lc];                \
        pfB[q] = Bsrc[(mrow0 + r) * DIM + (Dz) + lc];                \
    }                                                                \
    if (t < DK) pfW = w3[(Dz) + t];                                  \
} while (0)

#define STORC(buf) do {                                              \
    _Pragma("unroll")                                                \
    for (int q = 0; q < 8; q++) {                                    \
        int r = lr + 8 * q;                                          \
        sA[buf][lc][r] = pfA[q];                                     \
        sB[buf][lc][r] = pfB[q];                                     \
    }                                                                \
    if (t < DK) sW[buf][t] = pfW;                                    \
} while (0)

    LOADC(0);
    STORC(0);
    __syncthreads();

    for (int c = 0; c < NCHUNK; c++) {
        const int cur = c & 1;
        if (c < NCHUNK - 1) LOADC((c + 1) * DK);   // LDGs land during compute

        // ---- dot via tf32 mma first (HMMA latency overlaps min loop) ----
#pragma unroll
        for (int ks = 0; ks < 8; ks++) {
            const int k0 = ks * 8;
            unsigned fa0 = __float_as_uint(sA[cur][k0 + la    ][nb + lg]);
            unsigned fa1 = __float_as_uint(sA[cur][k0 + la    ][nb + lg + 8]);
            unsigned fa2 = __float_as_uint(sA[cur][k0 + la + 4][nb + lg]);
            unsigned fa3 = __float_as_uint(sA[cur][k0 + la + 4][nb + lg + 8]);
            unsigned fb0 = __float_as_uint(sB[cur][k0 + la    ][mb + lg]);
            unsigned fb1 = __float_as_uint(sB[cur][k0 + la + 4][mb + lg]);
            unsigned fc0 = __float_as_uint(sB[cur][k0 + la    ][mb + lg + 8]);
            unsigned fc1 = __float_as_uint(sB[cur][k0 + la + 4][mb + lg + 8]);
            mma_tf32(D0, fa0, fa1, fa2, fa3, fb0, fb1);   // cols mb..mb+7
            mma_tf32(D1, fa0, fa1, fa2, fa3, fc0, fc1);   // cols mb+8..mb+15
        }

        // ---- min-term scalar loop at R9-optimal coords (3 LDS/kk) ----
#pragma unroll 16
        for (int kk = 0; kk < DK; kk++) {
            float2 av = *(const float2*)&sA[cur][kk][ty * 2];
            float4 bv = *(const float4*)&sB[cur][kk][tx * 4];
            float a[2] = {av.x, av.y};
            float b[4] = {bv.x, bv.y, bv.z, bv.w};
            float wv = sW[cur][kk];
#pragma unroll
            for (int i = 0; i < 2; i++)
#pragma unroll
                for (int j = 0; j < 4; j++)
                    mnv[i][j] = fmaf(fminf(a[i], b[j]), wv, mnv[i][j]);
        }

        if (c < NCHUNK - 1) STORC(1 - cur);
        __syncthreads();
    }

    // ---- exchange: move min accumulators to mma D-fragment coords ----
    // sX aliases the sA region (dead after the final barrier above)
#pragma unroll
    for (int i = 0; i < 2; i++)
#pragma unroll
        for (int j = 0; j < 4; j++)
            sX[ty * 2 + i][tx * 4 + j] = mnv[i][j];
    __syncthreads();
    float mn2[2][4];
#pragma unroll
    for (int i = 0; i < 2; i++)
#pragma unroll
        for (int j = 0; j < 4; j++)
            mn2[i][j] = sX[nb + lg + 8 * i][mb + 2 * la + (j & 1) + 8 * (j >> 1)];

    // dot at mma coords
    float dotv[2][4];
    dotv[0][0] = D0[0]; dotv[0][1] = D0[1]; dotv[1][0] = D0[2]; dotv[1][1] = D0[3];
    dotv[0][2] = D1[0]; dotv[0][3] = D1[1]; dotv[1][2] = D1[2]; dotv[1][3] = D1[3];

    // ---- epilogue (mma coords) ----
    int gn[2];
    float rn_n[2], t1v[2], rn_m[4], t2v[4];
#pragma unroll
    for (int i = 0; i < 2; i++) {
        gn[i] = n0 + nb + lg + 8 * i;
        rn_n[i] = g_rnorm[gn[i]];
        t1v[i]  = g_t1[gn[i]];     // includes s3[n]
    }
#pragma unroll
    for (int j = 0; j < 4; j++) {
        int gm = m0 + mb + 2 * la + (j & 1) + 8 * (j >> 1);
        rn_m[j] = g_rnorm[gm];
        t2v[j]  = g_t2[gm];        // includes s3[m]
    }
    float bias = __ldg(bptr);

    float part = 0.f;

    if (!pos_half) {
        // ---- negative half: bce(label 0) + deno ----
        float bce = 0.f, dl[2] = {0.f, 0.f};
#pragma unroll
        for (int i = 0; i < 2; i++) {
#pragma unroll
            for (int j = 0; j < 4; j++) {
                float cc = dotv[i][j] * rn_n[i] * rn_m[j];
                float logit = t1v[i] + t2v[j] - 2.f * mn2[i][j] + bias;
                bce += sp(logit);
                dl[i] += expf(cc);
            }
        }
        // reduce over the 4 lanes (la) sharing each row
#pragma unroll
        for (int i = 0; i < 2; i++) {
            float v = dl[i];
            v += __shfl_xor_sync(0xffffffffu, v, 1);
            v += __shfl_xor_sync(0xffffffffu, v, 2);
            if (la == 0) atomicAdd(&g_deno[gn[i]], v);
        }
        __threadfence();                       // publish deno before negdone arrive
        part = bce * (1.0f / (float)NALL);
    } else {
        // ---- positive half: wait for deno, then bce(label 1) + contrastive ----
        if (t == 0) {
            while (atomicCAS(&g_negdone, 64u, 64u) != 64u) { __nanosleep(200); }
        }
        __syncthreads();
        __threadfence();
        float dn[2];
#pragma unroll
        for (int i = 0; i < 2; i++) dn[i] = __ldcg(&g_deno[gn[i]]);

        float bce = 0.f, l1 = 0.f;
#pragma unroll
        for (int i = 0; i < 2; i++) {
#pragma unroll
            for (int j = 0; j < 4; j++) {
                float cc = dotv[i][j] * rn_n[i] * rn_m[j];
                float logit = t1v[i] + t2v[j] - 2.f * mn2[i][j] + bias;
                bce += sp(-logit);
                l1 += logf(dn[i] + expf(cc) + EPSV) - cc;  // -log(e^c/(deno+e^c+eps))
            }
        }
        part = bce * (1.0f / (float)NALL) + l1;
    }

    // ---- block reduce + global accumulate + completion protocol ----
    float v = warp_sum(part);
    if ((t & 31) == 0) sRed[t >> 5] = v;
    __syncthreads();
    if (t == 0) {
        float s = 0.f;
#pragma unroll
        for (int k = 0; k < 16; k++) s += sRed[k];
        atomicAdd(&g_total, s);
        __threadfence();
        if (!pos_half) atomicAdd(&g_negdone, 1u);
        unsigned old = atomicAdd(&g_alldone, 1u);
        if (old == 127u) {
            __threadfence();
            out[0] = atomicAdd(&g_total, 0.f);
        }
    }
}

// ---------------- launch ----------------
extern "C" void kernel_launch(void* const* d_in, const int* in_sizes, int n_in,
                              void* d_out, int out_size) {
    const float* pos = (const float*)d_in[0];   // [512,512]
    const float* neg = (const float*)d_in[1];   // [512,512]
    const float* w   = (const float*)d_in[2];   // [1,1536]
    const float* b   = (const float*)d_in[3];   // [1]
    float* out = (float*)d_out;

    cudaFuncSetAttribute(pair_kernel,
                         cudaFuncAttributeMaxDynamicSharedMemorySize, SMEM_BYTES);

    row_kernel<<<NALL, 128>>>(pos, neg, w);
    dim3 grid(NALL / TILE, NPOS / TILE);        // (16, 8) — one wave, 128 blocks
    pair_kernel<<<grid, NTHR, SMEM_BYTES>>>(pos, neg, w, b, out);
}

// round 12
// speedup vs baseline: 1.1855x; 1.0860x over previous
#include <cuda_runtime.h>
#include <math.h>

#define NPOS 512
#define NALL 1024
#define DIM  512
#define EPSV 1e-5f
#define COSEPS 1e-8f
#define TILE 64
#define DK   64           // k-chunk, double-buffered
#define SPAD 68           // padded smem row (floats), 272B = 16B-aligned
#define NTHR 512
#define NCHUNK (DIM / DK) // 8

#define SMEM_FLOATS (4 * DK * SPAD + 2 * DK)
#define SMEM_BYTES  (SMEM_FLOATS * 4)

// ---------------- device scratch ----------------
__device__ float g_rnorm[NALL];
__device__ float g_t1[NPOS];     // t1 + s3 (pos rows)
__device__ float g_t2[NALL];     // t2 + s3 (all rows)
__device__ float g_deno[NPOS];
__device__ float g_total;
__device__ unsigned g_negdone;
__device__ unsigned g_alldone;

__device__ __forceinline__ float warp_sum(float v) {
#pragma unroll
    for (int o = 16; o; o >>= 1) v += __shfl_xor_sync(0xffffffffu, v, o);
    return v;
}

__device__ __forceinline__ float sp(float x) {   // softplus, stable
    return fmaxf(x, 0.f) + log1pf(expf(-fabsf(x)));
}

// ---------------- kernel 1: per-row norm, t1+s3, t2+s3 (+ scratch init) --------
__global__ void row_kernel(const float* __restrict__ pos,
                           const float* __restrict__ neg,
                           const float* __restrict__ w) {
    int row = blockIdx.x;                       // 0..1023
    int t = threadIdx.x;                        // 128
    if (t == 0) {
        if (row < NPOS) g_deno[row] = 0.f;
        if (row == 0) { g_total = 0.f; g_negdone = 0u; g_alldone = 0u; }
    }
    const float* src = (row < NPOS) ? (pos + row * DIM) : (neg + (row - NPOS) * DIM);
    float4 v  = ((const float4*)src)[t];
    float4 u1 = ((const float4*)w)[t];
    float4 u2 = ((const float4*)(w + DIM))[t];
    float4 u3 = ((const float4*)(w + 2 * DIM))[t];
    float ss = v.x * v.x; ss = fmaf(v.y, v.y, ss); ss = fmaf(v.z, v.z, ss); ss = fmaf(v.w, v.w, ss);
    float d1 = v.x * u1.x; d1 = fmaf(v.y, u1.y, d1); d1 = fmaf(v.z, u1.z, d1); d1 = fmaf(v.w, u1.w, d1);
    float d2 = v.x * u2.x; d2 = fmaf(v.y, u2.y, d2); d2 = fmaf(v.z, u2.z, d2); d2 = fmaf(v.w, u2.w, d2);
    float d3 = v.x * u3.x; d3 = fmaf(v.y, u3.y, d3); d3 = fmaf(v.z, u3.z, d3); d3 = fmaf(v.w, u3.w, d3);
    ss = warp_sum(ss); d1 = warp_sum(d1); d2 = warp_sum(d2); d3 = warp_sum(d3);
    __shared__ float red[4][4];
    int wid = t >> 5, lid = t & 31;
    if (lid == 0) { red[0][wid] = ss; red[1][wid] = d1; red[2][wid] = d2; red[3][wid] = d3; }
    __syncthreads();
    if (t == 0) {
        float S  = red[0][0] + red[0][1] + red[0][2] + red[0][3];
        float D1 = red[1][0] + red[1][1] + red[1][2] + red[1][3];
        float D2 = red[2][0] + red[2][1] + red[2][2] + red[2][3];
        float D3 = red[3][0] + red[3][1] + red[3][2] + red[3][3];
        g_rnorm[row] = 1.f / fmaxf(sqrtf(S), COSEPS);
        g_t2[row] = D2 + D3;                    // t2 + s3
        if (row < NPOS) g_t1[row] = D1 + D3;    // t1 + s3
    }
}

// ---------------- kernel 2: fused pair kernel ----------------
// grid (16, 8): bx<8 -> pos-vs-pos (loss1 + bce), bx>=8 -> pos-vs-neg (deno + bce)
// 512 threads, scalar 2n x 4m micro-tile; double-buffered DK=64 chunks.
// A smem [row][d] (vector a loads), B smem [d][col] (conflict-free b loads),
// W vectorized. logit = (t1+s3)[n] + (t2+s3)[m] - 2*sum_d w_d*min(a,b) + bias
__global__ void __launch_bounds__(NTHR, 1) pair_kernel(
    const float* __restrict__ pos, const float* __restrict__ neg,
    const float* __restrict__ w, const float* __restrict__ bptr,
    float* __restrict__ out)
{
    extern __shared__ float smem[];
    float (*sA)[TILE][SPAD] = (float (*)[TILE][SPAD])(smem);            // [buf][row][d]
    float (*sB)[DK][SPAD]   = (float (*)[DK][SPAD])(smem + 2 * TILE * SPAD); // [buf][d][col]
    float (*sW)[DK]         = (float (*)[DK])(smem + 4 * DK * SPAD);
    __shared__ float sRed[16];

    const int t  = threadIdx.x;
    const int tx = t & 15;           // m: 4 cols each
    const int ty = t >> 4;           // n: 2 rows each (0..31)
    const int n0 = blockIdx.y * TILE;
    const int m0 = blockIdx.x * TILE;
    const bool pos_half = (m0 < NPOS);
    const float* Bsrc = pos_half ? pos : neg;
    const int mrow0 = pos_half ? m0 : (m0 - NPOS);
    const float* w3 = w + 2 * DIM;

    float dotv[2][4], mnv[2][4];
#pragma unroll
    for (int i = 0; i < 2; i++)
#pragma unroll
        for (int j = 0; j < 4; j++) { dotv[i][j] = 0.f; mnv[i][j] = 0.f; }

    // A loader: row-contiguous float4s (coalesced LDG.128, STS.128)
    const int arow = t >> 3;         // 0..63
    const int adq  = (t & 7) * 8;    // 0..56
    // B loader: R9 mapping (coalesced scalar LDG, transposed STS)
    const int lc = t & 63;           // d within chunk
    const int lr = t >> 6;           // 0..7

    float4 pfA0, pfA1;
    float pfB[8];
    float4 pfW;
#define LOADC(Dz) do {                                                    \
    pfA0 = *(const float4*)(pos + (n0 + arow) * DIM + (Dz) + adq);        \
    pfA1 = *(const float4*)(pos + (n0 + arow) * DIM + (Dz) + adq + 4);    \
    _Pragma("unroll")                                                     \
    for (int q = 0; q < 8; q++)                                           \
        pfB[q] = Bsrc[(mrow0 + lr + 8 * q) * DIM + (Dz) + lc];            \
    if (t < 16) pfW = *(const float4*)(w3 + (Dz) + t * 4);                \
} while (0)

#define STORC(buf) do {                                                   \
    *(float4*)&sA[buf][arow][adq]     = pfA0;                             \
    *(float4*)&sA[buf][arow][adq + 4] = pfA1;                             \
    _Pragma("unroll")                                                     \
    for (int q = 0; q < 8; q++)                                           \
        sB[buf][lc][lr + 8 * q] = pfB[q];                                 \
    if (t < 16) *(float4*)&sW[buf][t * 4] = pfW;                          \
} while (0)

    LOADC(0);
    STORC(0);
    __syncthreads();

    for (int c = 0; c < NCHUNK; c++) {
        const int cur = c & 1;
        if (c < NCHUNK - 1) LOADC((c + 1) * DK);   // LDGs land during compute

#pragma unroll 4
        for (int kg = 0; kg < DK / 4; kg++) {      // 16 groups of 4 kk
            const float4 wv4 = *(const float4*)&sW[cur][kg * 4];
            const float4 a0v = *(const float4*)&sA[cur][ty * 2]    [kg * 4];
            const float4 a1v = *(const float4*)&sA[cur][ty * 2 + 1][kg * 4];
            const float aw[2][4] = {{a0v.x, a0v.y, a0v.z, a0v.w},
                                    {a1v.x, a1v.y, a1v.z, a1v.w}};
            const float wk[4] = {wv4.x, wv4.y, wv4.z, wv4.w};
#pragma unroll
            for (int u = 0; u < 4; u++) {
                float4 bv = *(const float4*)&sB[cur][kg * 4 + u][tx * 4];
                float b[4] = {bv.x, bv.y, bv.z, bv.w};
#pragma unroll
                for (int i = 0; i < 2; i++)
#pragma unroll
                    for (int j = 0; j < 4; j++) {
                        dotv[i][j] = fmaf(aw[i][u], b[j], dotv[i][j]);
                        mnv[i][j]  = fmaf(fminf(aw[i][u], b[j]), wk[u], mnv[i][j]);
                    }
            }
        }

        if (c < NCHUNK - 1) STORC(1 - cur);
        __syncthreads();
    }

    // ---- epilogue ----
    int gn[2];
    float rn_n[2], t1v[2], rn_m[4], t2v[4];
#pragma unroll
    for (int i = 0; i < 2; i++) {
        gn[i] = n0 + ty * 2 + i;
        rn_n[i] = g_rnorm[gn[i]];
        t1v[i]  = g_t1[gn[i]];     // includes s3[n]
    }
#pragma unroll
    for (int j = 0; j < 4; j++) {
        int gm = m0 + tx * 4 + j;
        rn_m[j] = g_rnorm[gm];
        t2v[j]  = g_t2[gm];        // includes s3[m]
    }
    float bias = __ldg(bptr);

    float part = 0.f;

    if (!pos_half) {
        // ---- negative half: bce(label 0) + deno ----
        float bce = 0.f, dl[2] = {0.f, 0.f};
#pragma unroll
        for (int i = 0; i < 2; i++) {
#pragma unroll
            for (int j = 0; j < 4; j++) {
                float cc = dotv[i][j] * rn_n[i] * rn_m[j];
                float logit = t1v[i] + t2v[j] - 2.f * mnv[i][j] + bias;
                bce += sp(logit);
                dl[i] += expf(cc);
            }
        }
        // reduce across the 16 tx-lanes sharing each n-row
#pragma unroll
        for (int i = 0; i < 2; i++) {
            float v = dl[i];
            v += __shfl_xor_sync(0xffffffffu, v, 1);
            v += __shfl_xor_sync(0xffffffffu, v, 2);
            v += __shfl_xor_sync(0xffffffffu, v, 4);
            v += __shfl_xor_sync(0xffffffffu, v, 8);
            if (tx == 0) atomicAdd(&g_deno[gn[i]], v);
        }
        __threadfence();                       // publish deno before negdone arrive
        part = bce * (1.0f / (float)NALL);
    } else {
        // ---- positive half: wait for deno, then bce(label 1) + contrastive ----
        if (t == 0) {
            while (atomicCAS(&g_negdone, 64u, 64u) != 64u) { __nanosleep(200); }
        }
        __syncthreads();
        __threadfence();
        float dn[2];
#pragma unroll
        for (int i = 0; i < 2; i++) dn[i] = __ldcg(&g_deno[gn[i]]);

        float bce = 0.f, l1 = 0.f;
#pragma unroll
        for (int i = 0; i < 2; i++) {
#pragma unroll
            for (int j = 0; j < 4; j++) {
                float cc = dotv[i][j] * rn_n[i] * rn_m[j];
                float logit = t1v[i] + t2v[j] - 2.f * mnv[i][j] + bias;
                bce += sp(-logit);
                l1 += logf(dn[i] + expf(cc) + EPSV) - cc;  // -log(e^c/(deno+e^c+eps))
            }
        }
        part = bce * (1.0f / (float)NALL) + l1;
    }

    // ---- block reduce + global accumulate + completion protocol ----
    float v = warp_sum(part);
    if ((t & 31) == 0) sRed[t >> 5] = v;
    __syncthreads();
    if (t == 0) {
        float s = 0.f;
#pragma unroll
        for (int k = 0; k < 16; k++) s += sRed[k];
        atomicAdd(&g_total, s);
        __threadfence();
        if (!pos_half) atomicAdd(&g_negdone, 1u);
        unsigned old = atomicAdd(&g_alldone, 1u);
        if (old == 127u) {
            __threadfence();
            out[0] = atomicAdd(&g_total, 0.f);
        }
    }
}

// ---------------- launch ----------------
extern "C" void kernel_launch(void* const* d_in, const int* in_sizes, int n_in,
                              void* d_out, int out_size) {
    const float* pos = (const float*)d_in[0];   // [512,512]
    const float* neg = (const float*)d_in[1];   // [512,512]
    const float* w   = (const float*)d_in[2];   // [1,1536]
    const float* b   = (const float*)d_in[3];   // [1]
    float* out = (float*)d_out;

    cudaFuncSetAttribute(pair_kernel,
                         cudaFuncAttributeMaxDynamicSharedMemorySize, SMEM_BYTES);

    row_kernel<<<NALL, 128>>>(pos, neg, w);
    dim3 grid(NALL / TILE, NPOS / TILE);        // (16, 8) — one wave, 128 blocks
    pair_kernel<<<grid, NTHR, SMEM_BYTES>>>(pos, neg, w, b, out);
}